// round 12
// baseline (speedup 1.0000x reference)
#include <cuda_runtime.h>
#include <cuda_bf16.h>
#include <cstdint>

#define MSL 256
#define EMB 1024
#define NHID 64
#define NSLAB 4
#define DSLAB (EMB / NSLAB)   // 256
#define NCHUNK (DSLAB / 16)   // 16 chunks of 16 d-values (4KB) per block
#define DEPTH 5               // ring slots; DEPTH-1 = 4 chunks in flight
#define NEGF (-1e20f)

// Transposed scratch for coalesced reduction: [in/mem][slab][k][pos]
__device__ float g_part[2][NSLAB][NHID][MSL];
// Reduced + ReLU'd hidden vectors. [in/mem][k]
__device__ float g_h[2][NHID];

// ---------------------------------------------------------------------------
// Kernel A: fused dual GEMV over w1, cp.async-pipelined.
// grid = 1024 (pos = b>>2, slab = b&3), block = 256 threads.
// 5-slot x 4KB SMEM ring, 4 chunks committed ahead: in-flight bytes live in
// SMEM (up to 16KB/block), decoupling MLP from registers/occupancy.
// ONE barrier per chunk: the slot written at iter c ((c+4)%5 == (c-1)%5) had
// its last reader at iter c-1, and iter c's barrier fences those reads.
// Reduction scratch aliases the ring after the loop (keeps 8 blocks/SM).
// ---------------------------------------------------------------------------
__global__ __launch_bounds__(256) void gemv_kernel(
    const int* __restrict__ toks_in, int n_toks,
    const int* __restrict__ toks_mem,
    const float* __restrict__ emb,
    const float* __restrict__ w1)
{
    __shared__ float4 wbuf[DEPTH][256];     // 20KB ring (reused as reduction scratch)
    __shared__ float s_in[DSLAB];
    __shared__ float s_mem[DSLAB];

    const int pos    = blockIdx.x >> 2;
    const int slab   = blockIdx.x & 3;
    const int d_base = slab * DSLAB;
    const int t      = threadIdx.x;

    const float4* wp =
        (const float4*)(w1 + ((size_t)pos * EMB + d_base) * NHID) + t;
    const unsigned sbase = (unsigned)__cvta_generic_to_shared(&wbuf[0][t]);

    // Prologue: commit chunks 0..3 (4 groups in flight).
    #pragma unroll
    for (int s = 0; s < DEPTH - 1; ++s) {
        asm volatile("cp.async.cg.shared.global [%0], [%1], 16;\n"
                     :: "r"(sbase + s * 4096), "l"(wp + s * 256));
        asm volatile("cp.async.commit_group;\n");
    }

    // Stage the two 1KB embedding slab segments (overlaps the async copies).
    const int tok_in  = (pos < n_toks) ? toks_in[pos] : 0;  // PAD = 0
    const int tok_mem = toks_mem[pos];
    if (t < 64) {
        ((float4*)s_in)[t] =
            ((const float4*)(emb + (size_t)tok_in * EMB + d_base))[t];
    } else if (t < 128) {
        ((float4*)s_mem)[t - 64] =
            ((const float4*)(emb + (size_t)tok_mem * EMB + d_base))[t - 64];
    }

    const int j_off = t >> 4;          // 0..15  (d stripe)
    const int k0    = (t & 15) * 4;    // 0,4,...,60

    float4 ai = make_float4(0.f, 0.f, 0.f, 0.f);
    float4 am = make_float4(0.f, 0.f, 0.f, 0.f);

    #pragma unroll
    for (int c = 0; c < NCHUNK; ++c) {
        // <= DEPTH-2 groups pending  =>  chunk c's copy has landed.
        asm volatile("cp.async.wait_group %0;\n" :: "n"(DEPTH - 2));
        __syncthreads();   // copy visible to all; prior slot reads fenced

        float4 w = wbuf[c % DEPTH][t];
        int   d  = c * 16 + j_off;
        float a  = s_in[d];
        float b  = s_mem[d];
        ai.x += a * w.x; ai.y += a * w.y; ai.z += a * w.z; ai.w += a * w.w;
        am.x += b * w.x; am.y += b * w.y; am.z += b * w.z; am.w += b * w.w;

        if (c + DEPTH - 1 < NCHUNK) {
            asm volatile("cp.async.cg.shared.global [%0], [%1], 16;\n"
                         :: "r"(sbase + ((c + DEPTH - 1) % DEPTH) * 4096),
                            "l"(wp + (c + DEPTH - 1) * 256));
        }
        asm volatile("cp.async.commit_group;\n");  // uniform group accounting
    }

    // All chunks consumed; no copies outstanding. Reuse the ring as scratch.
    __syncthreads();
    float* red = (float*)&wbuf[0][0];   // [0..1023]=in, [1024..2047]=mem
    red[       j_off * NHID + k0 + 0] = ai.x;
    red[       j_off * NHID + k0 + 1] = ai.y;
    red[       j_off * NHID + k0 + 2] = ai.z;
    red[       j_off * NHID + k0 + 3] = ai.w;
    red[1024 + j_off * NHID + k0 + 0] = am.x;
    red[1024 + j_off * NHID + k0 + 1] = am.y;
    red[1024 + j_off * NHID + k0 + 2] = am.z;
    red[1024 + j_off * NHID + k0 + 3] = am.w;
    __syncthreads();

    if (t < NHID) {
        float si = 0.f, sm = 0.f;
        #pragma unroll
        for (int r = 0; r < 16; ++r) {
            si += red[       r * NHID + t];
            sm += red[1024 + r * NHID + t];
        }
        g_part[0][slab][t][pos] = si;
        g_part[1][slab][t][pos] = sm;
    }

    cudaTriggerProgrammaticLaunchCompletion();
}

// ---------------------------------------------------------------------------
// Kernel B: reduce g_part over (slab, pos) -> +b1 -> ReLU -> g_h.
// grid = 128, block = 256. PDL: b1 prologue before the grid-dep sync.
// ---------------------------------------------------------------------------
__global__ __launch_bounds__(256) void reduce_kernel(
    const float* __restrict__ b1)
{
    __shared__ float warp_sums[8];
    const int s = blockIdx.x >> 6;     // 0..1
    const int k = blockIdx.x & 63;     // 0..63
    const int t = threadIdx.x;

    float bias = b1[k];                // independent of upstream

    cudaGridDependencySynchronize();   // wait for gemv grid completion

    float v = g_part[s][0][k][t] + g_part[s][1][k][t]
            + g_part[s][2][k][t] + g_part[s][3][k][t];

    #pragma unroll
    for (int off = 16; off > 0; off >>= 1)
        v += __shfl_down_sync(0xffffffffu, v, off);
    if ((t & 31) == 0) warp_sums[t >> 5] = v;
    __syncthreads();
    if (t == 0) {
        float sum = 0.f;
        #pragma unroll
        for (int w = 0; w < 8; ++w) sum += warp_sums[w];
        g_h[s][k] = fmaxf(sum + bias, 0.f);
    }

    cudaTriggerProgrammaticLaunchCompletion();
}

// ---------------------------------------------------------------------------
// Register-resident bitonic sort of 512 u64 keys, 512 threads. j<32 stages
// are pure __shfl_xor; only j>=32 stages round-trip through SMEM. Ascending.
// ---------------------------------------------------------------------------
__device__ __forceinline__ void bitonic512_reg(
    unsigned long long& v, unsigned long long* keys)
{
    const int i = threadIdx.x;
    #pragma unroll
    for (int k = 2; k <= 512; k <<= 1) {
        #pragma unroll
        for (int j = k >> 1; j > 0; j >>= 1) {
            unsigned long long o;
            if (j < 32) {
                o = __shfl_xor_sync(0xffffffffu, v, j);
            } else {
                __syncthreads();           // protect prior reads of keys[]
                keys[i] = v;
                __syncthreads();
                o = keys[i ^ j];
            }
            bool keep_min = (((i & j) == 0) == ((i & k) == 0));
            v = keep_min ? (v < o ? v : o) : (v > o ? v : o);
        }
    }
}

// ---------------------------------------------------------------------------
// Kernel C: layer2 + sigmoid -> PAD mask -> dedup + top-k via two
// register-bitonic sorts -> emit. 1 block, 512 threads.
// PDL: tokens/b2/w2 preloaded into registers before the grid-dep sync.
// ---------------------------------------------------------------------------
__global__ __launch_bounds__(512) void final_kernel(
    const int* __restrict__ toks_in, int n_toks,
    const int* __restrict__ toks_mem,
    const float* __restrict__ w2,
    const float* __restrict__ b2,
    float* __restrict__ out)
{
    __shared__ float h_sh[2][NHID];
    __shared__ unsigned long long keys[512];

    const int t   = threadIdx.x;
    const int pos = t & 255;
    const int sel = t >> 8;            // 0 = input scores, 1 = memory scores

    // ---- prologue: everything independent of g_h ----
    int   tok  = sel ? toks_mem[pos] : ((pos < n_toks) ? toks_in[pos] : 0);
    float bias = b2[pos];
    float w2v[NHID];
    #pragma unroll
    for (int k = 0; k < NHID; ++k)
        w2v[k] = w2[k * MSL + pos];    // coalesced; 2nd half L1-hits

    cudaGridDependencySynchronize();   // wait for reduce grid completion

    if (t < 2 * NHID) h_sh[t >> 6][t & 63] = g_h[t >> 6][t & 63];
    __syncthreads();

    // ---- layer 2 + sigmoid: one score per thread ----
    float acc = bias;
    {
        const float* hv = h_sh[sel];
        #pragma unroll
        for (int k = 0; k < NHID; ++k)
            acc += hv[k] * w2v[k];
    }
    float score = 1.f / (1.f + expf(-acc));

    // ---- key1 = (token asc, score desc); PAD -> sentinel ----
    unsigned sb = __float_as_uint(score);      // positive floats: monotonic
    unsigned long long v = (tok == 0) ? ~0ull
        : (((unsigned long long)(unsigned)tok << 32) | (unsigned)(~sb));

    // Sort1: groups duplicate tokens; best score first within each group.
    bitonic512_reg(v, keys);

    // ---- dedup: winner = first entry of its token run ----
    __syncthreads();
    keys[t] = v;
    __syncthreads();
    unsigned long long prev = (t == 0) ? ~0ull : keys[t - 1];
    bool win = (v != ~0ull) && (t == 0 || (v >> 32) != (prev >> 32));
    __syncthreads();                   // all reads done before sort2 reuses keys

    // key2 = swap halves: (~score_bits)<<32 | token -> asc = score desc, tok asc
    v = win ? ((v << 32) | (v >> 32)) : ~0ull;

    // Sort2: top-k order.
    bitonic512_reg(v, keys);

    // ---- emit first 256 (tokens as float, then scores) ----
    if (t < MSL) {
        bool present = (v != ~0ull);
        unsigned otok = (unsigned)v;                      // low 32
        float oscore  = __uint_as_float(~(unsigned)(v >> 32));
        out[t]       = present ? (float)otok : 0.0f;
        out[MSL + t] = present ? oscore : NEGF;
    }
}

extern "C" void kernel_launch(void* const* d_in, const int* in_sizes, int n_in,
                              void* d_out, int out_size)
{
    const int*   toks_in  = (const int*)  d_in[0];
    const int*   toks_mem = (const int*)  d_in[1];
    const float* emb      = (const float*)d_in[2];
    const float* w1       = (const float*)d_in[3];
    const float* b1       = (const float*)d_in[4];
    const float* w2       = (const float*)d_in[5];
    const float* b2       = (const float*)d_in[6];
    const int n_toks = in_sizes[0];

    gemv_kernel<<<MSL * NSLAB, 256>>>(toks_in, n_toks, toks_mem, emb, w1);

    cudaLaunchAttribute pdl[1];
    pdl[0].id = cudaLaunchAttributeProgrammaticStreamSerialization;
    pdl[0].val.programmaticStreamSerializationAllowed = 1;

    {
        cudaLaunchConfig_t cfg = {};
        cfg.gridDim  = dim3(128);
        cfg.blockDim = dim3(256);
        cfg.stream   = 0;
        cfg.attrs    = pdl;
        cfg.numAttrs = 1;
        cudaLaunchKernelEx(&cfg, reduce_kernel, b1);
    }
    {
        cudaLaunchConfig_t cfg = {};
        cfg.gridDim  = dim3(1);
        cfg.blockDim = dim3(512);
        cfg.stream   = 0;
        cfg.attrs    = pdl;
        cfg.numAttrs = 1;
        cudaLaunchKernelEx(&cfg, final_kernel, toks_in, n_toks, toks_mem,
                           w2, b2, (float*)d_out);
    }
}

// round 14
// speedup vs baseline: 1.1050x; 1.1050x over previous
#include <cuda_runtime.h>
#include <cuda_bf16.h>
#include <cstdint>

#define MSL 256
#define EMB 1024
#define NHID 64
#define NBLK 1024             // gemv blocks; one wave (<=148 SMs x 8)
#define NEGF (-1e20f)

// Per-block partial hidden vectors: [in/mem][k][block]
__device__ float g_part[2][NHID][NBLK];
// Reduced + ReLU'd hidden vectors. [in/mem][k]
__device__ float g_h[2][NHID];

// ---------------------------------------------------------------------------
// Kernel A: fused dual GEMV over w1, chip-wide moving-window access.
// grid = 1024, block = 256 threads. Chunk g = c*1024 + blockIdx (4KB each):
// at iteration c, ALL blocks read the contiguous 4MB slice [c*4MB,(c+1)*4MB)
// -> DRAM sees one sequential sweep instead of 1024 interleaved streams.
// Block b=(q=b>>6, r=b&63) covers pos = c*16+q (c=0..15) at d-group r; since
// h[k] sums over pos, the block accumulates all 16 chunks in registers and
// emits ONE [2][64] partial. Emb segments for its 16 positions are staged
// in 2KB SMEM up front.
// ---------------------------------------------------------------------------
__global__ __launch_bounds__(256) void gemv_kernel(
    const int* __restrict__ toks_in, int n_toks,
    const int* __restrict__ toks_mem,
    const float* __restrict__ emb,
    const float* __restrict__ w1)
{
    __shared__ float semb[16][2][16];   // [c][io][d_off]
    __shared__ int   stok[2][16];       // [io][c]
    __shared__ float red[2][16][NHID];  // stripe-reduction scratch

    const int b = blockIdx.x;
    const int q = b >> 6;              // 0..15  (pos phase)
    const int r = b & 63;              // 0..63  (d-group)
    const int t = threadIdx.x;

    // Tokens for my 16 positions (pos = c*16 + q).
    if (t < 32) {
        int c  = t & 15;
        int io = t >> 4;
        int pos = c * 16 + q;
        stok[io][c] = io ? toks_mem[pos]
                         : ((pos < n_toks) ? toks_in[pos] : 0);  // PAD = 0
    }
    __syncthreads();

    // Emb segments: emb[tok][r*16 .. r*16+16), 64B each, 4 threads/segment.
    if (t < 128) {
        int seg = t >> 2;              // 0..31
        int c   = seg >> 1;
        int io  = seg & 1;
        int l4  = t & 3;
        int tok = stok[io][c];
        const float4* src = (const float4*)(emb + (size_t)tok * EMB + r * 16);
        ((float4*)&semb[c][io][0])[l4] = src[l4];
    }
    __syncthreads();

    const float4* wp = (const float4*)w1 + (size_t)b * 256 + t;
    const int d_off = t >> 4;          // 0..15  (d stripe within the group)
    const int k0    = (t & 15) * 4;    // 0,4,...,60

    float4 ai = make_float4(0.f, 0.f, 0.f, 0.f);
    float4 am = make_float4(0.f, 0.f, 0.f, 0.f);

    #pragma unroll
    for (int c = 0; c < 16; ++c) {
        float4 w = wp[(size_t)c * 262144];  // chunk stride = 4MB / 16B
        float a  = semb[c][0][d_off];
        float bm = semb[c][1][d_off];
        ai.x += a  * w.x; ai.y += a  * w.y; ai.z += a  * w.z; ai.w += a  * w.w;
        am.x += bm * w.x; am.y += bm * w.y; am.z += bm * w.z; am.w += bm * w.w;
    }

    red[0][d_off][k0 + 0] = ai.x;
    red[0][d_off][k0 + 1] = ai.y;
    red[0][d_off][k0 + 2] = ai.z;
    red[0][d_off][k0 + 3] = ai.w;
    red[1][d_off][k0 + 0] = am.x;
    red[1][d_off][k0 + 1] = am.y;
    red[1][d_off][k0 + 2] = am.z;
    red[1][d_off][k0 + 3] = am.w;
    __syncthreads();

    if (t < NHID) {
        float si = 0.f, sm = 0.f;
        #pragma unroll
        for (int rr = 0; rr < 16; ++rr) {
            si += red[0][rr][t];
            sm += red[1][rr][t];
        }
        g_part[0][t][b] = si;
        g_part[1][t][b] = sm;
    }

    cudaTriggerProgrammaticLaunchCompletion();
}

// ---------------------------------------------------------------------------
// Kernel B: reduce g_part over the 1024 blocks -> +b1 -> ReLU -> g_h.
// grid = 128 (one block per (s,k)), block = 256; float4 coalesced loads.
// PDL: b1 prologue before the grid-dep sync. Fixed tree -> deterministic.
// ---------------------------------------------------------------------------
__global__ __launch_bounds__(256) void reduce_kernel(
    const float* __restrict__ b1)
{
    __shared__ float warp_sums[8];
    const int s = blockIdx.x >> 6;     // 0..1
    const int k = blockIdx.x & 63;     // 0..63
    const int t = threadIdx.x;

    float bias = b1[k];                // independent of upstream

    cudaGridDependencySynchronize();   // wait for gemv grid completion

    float4 v4 = ((const float4*)&g_part[s][k][0])[t];
    float v = (v4.x + v4.y) + (v4.z + v4.w);

    #pragma unroll
    for (int off = 16; off > 0; off >>= 1)
        v += __shfl_down_sync(0xffffffffu, v, off);
    if ((t & 31) == 0) warp_sums[t >> 5] = v;
    __syncthreads();
    if (t == 0) {
        float sum = 0.f;
        #pragma unroll
        for (int w = 0; w < 8; ++w) sum += warp_sums[w];
        g_h[s][k] = fmaxf(sum + bias, 0.f);
    }

    cudaTriggerProgrammaticLaunchCompletion();
}

// ---------------------------------------------------------------------------
// Register-resident bitonic sort of 512 u64 keys, 512 threads. j<32 stages
// are pure __shfl_xor; only j>=32 stages round-trip through SMEM. Ascending.
// ---------------------------------------------------------------------------
__device__ __forceinline__ void bitonic512_reg(
    unsigned long long& v, unsigned long long* keys)
{
    const int i = threadIdx.x;
    #pragma unroll
    for (int k = 2; k <= 512; k <<= 1) {
        #pragma unroll
        for (int j = k >> 1; j > 0; j >>= 1) {
            unsigned long long o;
            if (j < 32) {
                o = __shfl_xor_sync(0xffffffffu, v, j);
            } else {
                __syncthreads();           // protect prior reads of keys[]
                keys[i] = v;
                __syncthreads();
                o = keys[i ^ j];
            }
            bool keep_min = (((i & j) == 0) == ((i & k) == 0));
            v = keep_min ? (v < o ? v : o) : (v > o ? v : o);
        }
    }
}

// ---------------------------------------------------------------------------
// Kernel C: layer2 + sigmoid -> PAD mask -> dedup + top-k via two
// register-bitonic sorts -> emit. 1 block, 512 threads.
// PDL: tokens/b2/w2 preloaded into registers before the grid-dep sync.
// ---------------------------------------------------------------------------
__global__ __launch_bounds__(512) void final_kernel(
    const int* __restrict__ toks_in, int n_toks,
    const int* __restrict__ toks_mem,
    const float* __restrict__ w2,
    const float* __restrict__ b2,
    float* __restrict__ out)
{
    __shared__ float h_sh[2][NHID];
    __shared__ unsigned long long keys[512];

    const int t   = threadIdx.x;
    const int pos = t & 255;
    const int sel = t >> 8;            // 0 = input scores, 1 = memory scores

    // ---- prologue: everything independent of g_h ----
    int   tok  = sel ? toks_mem[pos] : ((pos < n_toks) ? toks_in[pos] : 0);
    float bias = b2[pos];
    float w2v[NHID];
    #pragma unroll
    for (int k = 0; k < NHID; ++k)
        w2v[k] = w2[k * MSL + pos];    // coalesced; 2nd half L1-hits

    cudaGridDependencySynchronize();   // wait for reduce grid completion

    if (t < 2 * NHID) h_sh[t >> 6][t & 63] = g_h[t >> 6][t & 63];
    __syncthreads();

    // ---- layer 2 + sigmoid: one score per thread ----
    float acc = bias;
    {
        const float* hv = h_sh[sel];
        #pragma unroll
        for (int k = 0; k < NHID; ++k)
            acc += hv[k] * w2v[k];
    }
    float score = 1.f / (1.f + expf(-acc));

    // ---- key1 = (token asc, score desc); PAD -> sentinel ----
    unsigned sb = __float_as_uint(score);      // positive floats: monotonic
    unsigned long long v = (tok == 0) ? ~0ull
        : (((unsigned long long)(unsigned)tok << 32) | (unsigned)(~sb));

    // Sort1: groups duplicate tokens; best score first within each group.
    bitonic512_reg(v, keys);

    // ---- dedup: winner = first entry of its token run ----
    __syncthreads();
    keys[t] = v;
    __syncthreads();
    unsigned long long prev = (t == 0) ? ~0ull : keys[t - 1];
    bool win = (v != ~0ull) && (t == 0 || (v >> 32) != (prev >> 32));
    __syncthreads();                   // all reads done before sort2 reuses keys

    // key2 = swap halves: (~score_bits)<<32 | token -> asc = score desc, tok asc
    v = win ? ((v << 32) | (v >> 32)) : ~0ull;

    // Sort2: top-k order.
    bitonic512_reg(v, keys);

    // ---- emit first 256 (tokens as float, then scores) ----
    if (t < MSL) {
        bool present = (v != ~0ull);
        unsigned otok = (unsigned)v;                      // low 32
        float oscore  = __uint_as_float(~(unsigned)(v >> 32));
        out[t]       = present ? (float)otok : 0.0f;
        out[MSL + t] = present ? oscore : NEGF;
    }
}

extern "C" void kernel_launch(void* const* d_in, const int* in_sizes, int n_in,
                              void* d_out, int out_size)
{
    const int*   toks_in  = (const int*)  d_in[0];
    const int*   toks_mem = (const int*)  d_in[1];
    const float* emb      = (const float*)d_in[2];
    const float* w1       = (const float*)d_in[3];
    const float* b1       = (const float*)d_in[4];
    const float* w2       = (const float*)d_in[5];
    const float* b2       = (const float*)d_in[6];
    const int n_toks = in_sizes[0];

    gemv_kernel<<<NBLK, 256>>>(toks_in, n_toks, toks_mem, emb, w1);

    cudaLaunchAttribute pdl[1];
    pdl[0].id = cudaLaunchAttributeProgrammaticStreamSerialization;
    pdl[0].val.programmaticStreamSerializationAllowed = 1;

    {
        cudaLaunchConfig_t cfg = {};
        cfg.gridDim  = dim3(128);
        cfg.blockDim = dim3(256);
        cfg.stream   = 0;
        cfg.attrs    = pdl;
        cfg.numAttrs = 1;
        cudaLaunchKernelEx(&cfg, reduce_kernel, b1);
    }
    {
        cudaLaunchConfig_t cfg = {};
        cfg.gridDim  = dim3(1);
        cfg.blockDim = dim3(512);
        cfg.stream   = 0;
        cfg.attrs    = pdl;
        cfg.numAttrs = 1;
        cudaLaunchKernelEx(&cfg, final_kernel, toks_in, n_toks, toks_mem,
                           w2, b2, (float*)d_out);
    }
}

// round 15
// speedup vs baseline: 1.2229x; 1.1067x over previous
#include <cuda_runtime.h>
#include <cuda_bf16.h>
#include <cstdint>

#define MSL 256
#define EMB 1024
#define NHID 64
#define NBLK 1024             // gemv blocks; one wave (<=148 SMs x 8)
#define VOCAB 32000
#define NEGF (-1e20f)

// Per-block partial hidden vectors: [in/mem][k][block]
__device__ float g_part[2][NHID][NBLK];
// Reduced + ReLU'd hidden vectors. [in/mem][k]
__device__ float g_h[2][NHID];

// ---------------------------------------------------------------------------
// Kernel A (proven, R14): fused dual GEMV over w1, chip-wide moving window.
// grid = 1024, block = 256. At iteration c all blocks read the contiguous
// 4MB slice [c*4MB,(c+1)*4MB). Block b=(q=b>>6, r=b&63) covers pos=c*16+q
// at d-group r, accumulating all 16 chunks in registers -> one [2][64]
// partial per block.
// ---------------------------------------------------------------------------
__global__ __launch_bounds__(256) void gemv_kernel(
    const int* __restrict__ toks_in, int n_toks,
    const int* __restrict__ toks_mem,
    const float* __restrict__ emb,
    const float* __restrict__ w1)
{
    __shared__ float semb[16][2][16];   // [c][io][d_off]
    __shared__ int   stok[2][16];       // [io][c]
    __shared__ float red[2][16][NHID];  // stripe-reduction scratch

    const int b = blockIdx.x;
    const int q = b >> 6;              // 0..15  (pos phase)
    const int r = b & 63;              // 0..63  (d-group)
    const int t = threadIdx.x;

    // Tokens for my 16 positions (pos = c*16 + q).
    if (t < 32) {
        int c  = t & 15;
        int io = t >> 4;
        int pos = c * 16 + q;
        stok[io][c] = io ? toks_mem[pos]
                         : ((pos < n_toks) ? toks_in[pos] : 0);  // PAD = 0
    }
    __syncthreads();

    // Emb segments: emb[tok][r*16 .. r*16+16), 64B each, 4 threads/segment.
    if (t < 128) {
        int seg = t >> 2;              // 0..31
        int c   = seg >> 1;
        int io  = seg & 1;
        int l4  = t & 3;
        int tok = stok[io][c];
        const float4* src = (const float4*)(emb + (size_t)tok * EMB + r * 16);
        ((float4*)&semb[c][io][0])[l4] = src[l4];
    }
    __syncthreads();

    const float4* wp = (const float4*)w1 + (size_t)b * 256 + t;
    const int d_off = t >> 4;          // 0..15  (d stripe within the group)
    const int k0    = (t & 15) * 4;    // 0,4,...,60

    float4 ai = make_float4(0.f, 0.f, 0.f, 0.f);
    float4 am = make_float4(0.f, 0.f, 0.f, 0.f);

    #pragma unroll
    for (int c = 0; c < 16; ++c) {
        float4 w = wp[(size_t)c * 262144];  // chunk stride = 4MB / 16B
        float a  = semb[c][0][d_off];
        float bm = semb[c][1][d_off];
        ai.x += a  * w.x; ai.y += a  * w.y; ai.z += a  * w.z; ai.w += a  * w.w;
        am.x += bm * w.x; am.y += bm * w.y; am.z += bm * w.z; am.w += bm * w.w;
    }

    red[0][d_off][k0 + 0] = ai.x;
    red[0][d_off][k0 + 1] = ai.y;
    red[0][d_off][k0 + 2] = ai.z;
    red[0][d_off][k0 + 3] = ai.w;
    red[1][d_off][k0 + 0] = am.x;
    red[1][d_off][k0 + 1] = am.y;
    red[1][d_off][k0 + 2] = am.z;
    red[1][d_off][k0 + 3] = am.w;
    __syncthreads();

    if (t < NHID) {
        float si = 0.f, sm = 0.f;
        #pragma unroll
        for (int rr = 0; rr < 16; ++rr) {
            si += red[0][rr][t];
            sm += red[1][rr][t];
        }
        g_part[0][t][b] = si;
        g_part[1][t][b] = sm;
    }

    cudaTriggerProgrammaticLaunchCompletion();
}

// ---------------------------------------------------------------------------
// Kernel B: reduce g_part over the 1024 blocks -> +b1 -> ReLU -> g_h.
// grid = 128 (one block per (s,k)), block = 256; float4 coalesced loads.
// PDL: triggers the dependent IMMEDIATELY after its own grid-dep sync, so
// final_kernel's fat prologue (125KB table init + w2 preload) overlaps this
// kernel's compute instead of serializing after it.
// ---------------------------------------------------------------------------
__global__ __launch_bounds__(256) void reduce_kernel(
    const float* __restrict__ b1)
{
    __shared__ float warp_sums[8];
    const int s = blockIdx.x >> 6;     // 0..1
    const int k = blockIdx.x & 63;     // 0..63
    const int t = threadIdx.x;

    float bias = b1[k];                // independent of upstream

    cudaGridDependencySynchronize();   // wait for gemv grid completion
    cudaTriggerProgrammaticLaunchCompletion();   // early: overlap final's prologue

    float4 v4 = ((const float4*)&g_part[s][k][0])[t];
    float v = (v4.x + v4.y) + (v4.z + v4.w);

    #pragma unroll
    for (int off = 16; off > 0; off >>= 1)
        v += __shfl_down_sync(0xffffffffu, v, off);
    if ((t & 31) == 0) warp_sums[t >> 5] = v;
    __syncthreads();
    if (t == 0) {
        float sum = 0.f;
        #pragma unroll
        for (int w = 0; w < 8; ++w) sum += warp_sums[w];
        g_h[s][k] = fmaxf(sum + bias, 0.f);
    }
}

// ---------------------------------------------------------------------------
// Register-resident bitonic sort of 512 u64 keys, 512 threads. j<32 stages
// are pure __shfl_xor; only j>=32 stages round-trip through SMEM. Ascending.
// ---------------------------------------------------------------------------
__device__ __forceinline__ void bitonic512_reg(
    unsigned long long& v, unsigned long long* keys)
{
    const int i = threadIdx.x;
    #pragma unroll
    for (int k = 2; k <= 512; k <<= 1) {
        #pragma unroll
        for (int j = k >> 1; j > 0; j >>= 1) {
            unsigned long long o;
            if (j < 32) {
                o = __shfl_xor_sync(0xffffffffu, v, j);
            } else {
                __syncthreads();           // protect prior reads of keys[]
                keys[i] = v;
                __syncthreads();
                o = keys[i ^ j];
            }
            bool keep_min = (((i & j) == 0) == ((i & k) == 0));
            v = keep_min ? (v < o ? v : o) : (v > o ? v : o);
        }
    }
}

// ---------------------------------------------------------------------------
// Kernel C: layer2 + sigmoid -> SMEM scatter-max dedup (vocab table) ->
// top-k via ONE register-bitonic sort -> emit. 1 block, 512 threads,
// 125KB dynamic SMEM table.
// Dedup: atomicMax(table[tok], score_bits) is exact & order-independent;
// the atomicExch claim picks exactly one winner per token, and any racers
// are bitwise ties -> emitted key identical -> deterministic output.
// ---------------------------------------------------------------------------
__global__ __launch_bounds__(512) void final_kernel(
    const int* __restrict__ toks_in, int n_toks,
    const int* __restrict__ toks_mem,
    const float* __restrict__ w2,
    const float* __restrict__ b2,
    float* __restrict__ out)
{
    extern __shared__ unsigned table[];        // VOCAB u32 (dynamic, 125KB)
    __shared__ float h_sh[2][NHID];
    __shared__ unsigned long long keys[512];

    const int t   = threadIdx.x;
    const int pos = t & 255;
    const int sel = t >> 8;            // 0 = input scores, 1 = memory scores

    // ---- prologue (overlaps reduce_kernel via early PDL trigger) ----
    int   tok  = sel ? toks_mem[pos] : ((pos < n_toks) ? toks_in[pos] : 0);
    float bias = b2[pos];
    float w2v[NHID];
    #pragma unroll
    for (int k = 0; k < NHID; ++k)
        w2v[k] = w2[k * MSL + pos];    // coalesced; 2nd half L1-hits

    // Zero the vocab table (scores are sigmoid > 0, so 0 = empty).
    uint4* t4 = (uint4*)table;
    #pragma unroll
    for (int i = t; i < VOCAB / 4; i += 512)
        t4[i] = make_uint4(0u, 0u, 0u, 0u);

    cudaGridDependencySynchronize();   // wait for reduce grid completion

    if (t < 2 * NHID) h_sh[t >> 6][t & 63] = g_h[t >> 6][t & 63];
    __syncthreads();                   // also fences the table init

    // ---- layer 2 + sigmoid: one score per thread ----
    float acc = bias;
    {
        const float* hv = h_sh[sel];
        #pragma unroll
        for (int k = 0; k < NHID; ++k)
            acc += hv[k] * w2v[k];
    }
    float score = 1.f / (1.f + expf(-acc));
    unsigned sb = __float_as_uint(score);   // positive floats: bits monotonic

    // ---- scatter-max dedup over the vocab table ----
    if (tok != 0) atomicMax(&table[tok], sb);
    __syncthreads();                   // all maxes visible before claims

    bool win = false;
    if (tok != 0 && table[tok] == sb) {
        unsigned old = atomicExch(&table[tok], 0xFFFFFFFFu);
        win = (old == sb);             // first claimer among bitwise ties
    }

    // key = (~score_bits)<<32 | token  -> ascending = score desc, token asc
    unsigned long long v = win
        ? ((((unsigned long long)(unsigned)(~sb)) << 32) | (unsigned)tok)
        : ~0ull;

    // Single sort: top-k order.
    bitonic512_reg(v, keys);

    // ---- emit first 256 (tokens as float, then scores) ----
    if (t < MSL) {
        bool present = (v != ~0ull);
        unsigned otok = (unsigned)v;                      // low 32
        float oscore  = __uint_as_float(~(unsigned)(v >> 32));
        out[t]       = present ? (float)otok : 0.0f;
        out[MSL + t] = present ? oscore : NEGF;
    }
}

extern "C" void kernel_launch(void* const* d_in, const int* in_sizes, int n_in,
                              void* d_out, int out_size)
{
    const int*   toks_in  = (const int*)  d_in[0];
    const int*   toks_mem = (const int*)  d_in[1];
    const float* emb      = (const float*)d_in[2];
    const float* w1       = (const float*)d_in[3];
    const float* b1       = (const float*)d_in[4];
    const float* w2       = (const float*)d_in[5];
    const float* b2       = (const float*)d_in[6];
    const int n_toks = in_sizes[0];

    const int table_bytes = VOCAB * (int)sizeof(unsigned);   // 128000
    cudaFuncSetAttribute(final_kernel,
                         cudaFuncAttributeMaxDynamicSharedMemorySize,
                         table_bytes);

    gemv_kernel<<<NBLK, 256>>>(toks_in, n_toks, toks_mem, emb, w1);

    cudaLaunchAttribute pdl[1];
    pdl[0].id = cudaLaunchAttributeProgrammaticStreamSerialization;
    pdl[0].val.programmaticStreamSerializationAllowed = 1;

    {
        cudaLaunchConfig_t cfg = {};
        cfg.gridDim  = dim3(128);
        cfg.blockDim = dim3(256);
        cfg.stream   = 0;
        cfg.attrs    = pdl;
        cfg.numAttrs = 1;
        cudaLaunchKernelEx(&cfg, reduce_kernel, b1);
    }
    {
        cudaLaunchConfig_t cfg = {};
        cfg.gridDim  = dim3(1);
        cfg.blockDim = dim3(512);
        cfg.stream   = 0;
        cfg.dynamicSmemBytes = (size_t)table_bytes;
        cfg.attrs    = pdl;
        cfg.numAttrs = 1;
        cudaLaunchKernelEx(&cfg, final_kernel, toks_in, n_toks, toks_mem,
                           w2, b2, (float*)d_out);
    }
}